// round 1
// baseline (speedup 1.0000x reference)
#include <cuda_runtime.h>
#include <cstddef>

// Problem constants (fixed by the dataset)
#define NMAX   400000
#define FDIM   128
#define KNBR   5
#define FP1    129   // 1 (weight-sum col) + FDIM

// Scratch accumulator: pushed[N][129]. ~206 MB, static device allocation
// (allowed; cudaMalloc is not).
__device__ float g_pushed[(size_t)NMAX * FP1];

// ---------------------------------------------------------------------------
// Phase 1: zero the accumulator (float4-vectorized; N*129 is divisible by 4)
// ---------------------------------------------------------------------------
__global__ void zero_kernel(int n4) {
    int i = blockIdx.x * blockDim.x + threadIdx.x;
    float4* p = reinterpret_cast<float4*>(g_pushed);
    if (i < n4) p[i] = make_float4(0.f, 0.f, 0.f, 0.f);
}

// ---------------------------------------------------------------------------
// Phase 2: scatter. One block per source row i (128 threads, one per feature).
// Each thread holds its feature value in a register and does K atomicAdds.
// The 129-float destination rows are contiguous -> warp atomics hit
// consecutive sectors, so RMW traffic stays near the 516B/row floor.
// ---------------------------------------------------------------------------
__global__ void scatter_kernel(const float* __restrict__ features,
                               const float* __restrict__ weights,
                               const int*   __restrict__ nidx,
                               int N) {
    const int i = blockIdx.x;
    const int t = threadIdx.x;
    const float f = features[(size_t)i * FDIM + t];

#pragma unroll
    for (int k = 0; k < KNBR; ++k) {
        const int idx = nidx[i * KNBR + k];      // broadcast load (same addr all lanes)
        if (idx >= 0) {
            const float wk = weights[i * KNBR + k];
            float* row = g_pushed + (size_t)idx * FP1;
            atomicAdd(row + 1 + t, wk * f);
            if (t == 0) atomicAdd(row, wk);      // the "ones" column
        }
    }
}

// ---------------------------------------------------------------------------
// Phase 3: gather + normalize. One block per output row j.
// wsum = relu(sel[0]); if wsum==0 -> 0.001; out = sel[1:]/wsum
// ---------------------------------------------------------------------------
__global__ void gather_kernel(const int* __restrict__ sel_idx,
                              float* __restrict__ out,
                              int n_up) {
    const int j = blockIdx.x;
    const int t = threadIdx.x;
    const int idx = sel_idx[j];
    const float* row = g_pushed + (size_t)idx * FP1;
    const float s0 = row[0];
    const float wsum = (s0 > 0.f) ? s0 : 0.001f;   // relu + fallback fused
    out[(size_t)j * FDIM + t] = row[1 + t] / wsum;
}

// ---------------------------------------------------------------------------
// Launch
// Inputs (metadata order): features [N,128] f32, weights_down [N,5] f32,
//                          nidx_down [N,5] i32, sel_idx_up [N_UP,1] i32
// Output: [N_UP, 128] f32
// ---------------------------------------------------------------------------
extern "C" void kernel_launch(void* const* d_in, const int* in_sizes, int n_in,
                              void* d_out, int out_size) {
    const float* features = (const float*)d_in[0];
    const float* weights  = (const float*)d_in[1];
    const int*   nidx     = (const int*)  d_in[2];
    const int*   sel_idx  = (const int*)  d_in[3];
    float*       out      = (float*)d_out;

    const int N    = in_sizes[0] / FDIM;
    const int N_UP = in_sizes[3];

    const int total4 = (int)(((size_t)N * FP1) / 4);
    zero_kernel<<<(total4 + 255) / 256, 256>>>(total4);
    scatter_kernel<<<N, FDIM>>>(features, weights, nidx, N);
    gather_kernel<<<N_UP, FDIM>>>(sel_idx, out, N_UP);
}

// round 2
// speedup vs baseline: 1.3513x; 1.3513x over previous
#include <cuda_runtime.h>
#include <cstddef>

// Problem constants (fixed by the dataset)
#define NMAX   400000
#define FDIM   128
#define KNBR   5
#define FP1    129   // 1 (weight-sum col) + FDIM

// Scratch: pushed[N][129] (~206 MB) + per-row "is selected" flag.
__device__ float         g_pushed[(size_t)NMAX * FP1];
__device__ unsigned char g_flag[NMAX];

// ---------------------------------------------------------------------------
// Phase 0a: clear flags (400 KB as ints)
// ---------------------------------------------------------------------------
__global__ void clear_flags_kernel(int n4) {
    int i = blockIdx.x * blockDim.x + threadIdx.x;
    if (i < n4) reinterpret_cast<int*>(g_flag)[i] = 0;
}

// ---------------------------------------------------------------------------
// Phase 0b: set flags for selected destination rows
// ---------------------------------------------------------------------------
__global__ void set_flags_kernel(const int* __restrict__ sel_idx, int n_up) {
    int j = blockIdx.x * blockDim.x + threadIdx.x;
    if (j < n_up) g_flag[sel_idx[j]] = 1;
}

// ---------------------------------------------------------------------------
// Phase 1: zero ONLY the selected rows (duplicates write 0 twice — benign).
// One warp-group of 128 threads per selected row; 129 floats per row.
// ---------------------------------------------------------------------------
__global__ void zero_sel_kernel(const int* __restrict__ sel_idx, int n_up) {
    const int j = blockIdx.x;
    if (j >= n_up) return;
    float* row = g_pushed + (size_t)sel_idx[j] * FP1;
    for (int t = threadIdx.x; t < FP1; t += blockDim.x) row[t] = 0.f;
}

// ---------------------------------------------------------------------------
// Phase 2: scatter, filtered by destination flag.
// One block per source row i (128 threads, one per feature).
// - read the 5 dest indices + flags first (broadcast loads)
// - if no live destination, exit before touching features (29% of rows)
// - atomics only to live rows (~22% of destinations)
// ---------------------------------------------------------------------------
__global__ void scatter_kernel(const float* __restrict__ features,
                               const float* __restrict__ weights,
                               const int*   __restrict__ nidx,
                               int N) {
    const int i = blockIdx.x;
    const int t = threadIdx.x;

    int  idxs[KNBR];
    bool live[KNBR];
    bool any = false;
#pragma unroll
    for (int k = 0; k < KNBR; ++k) {
        const int idx = nidx[i * KNBR + k];        // broadcast (same addr all lanes)
        idxs[k] = idx;
        const bool l = (idx >= 0) && (g_flag[idx] != 0);
        live[k] = l;
        any |= l;
    }
    if (!any) return;                               // skip feature load entirely

    const float f = features[(size_t)i * FDIM + t];

#pragma unroll
    for (int k = 0; k < KNBR; ++k) {
        if (live[k]) {
            const float wk = weights[i * KNBR + k];
            float* row = g_pushed + (size_t)idxs[k] * FP1;
            atomicAdd(row + 1 + t, wk * f);
            if (t == 0) atomicAdd(row, wk);         // the "ones" column
        }
    }
}

// ---------------------------------------------------------------------------
// Phase 3: gather + normalize. One block per output row j.
// wsum = relu(sel[0]); if wsum<=0 -> 0.001; out = sel[1:]/wsum
// ---------------------------------------------------------------------------
__global__ void gather_kernel(const int* __restrict__ sel_idx,
                              float* __restrict__ out,
                              int n_up) {
    const int j = blockIdx.x;
    const int t = threadIdx.x;
    const int idx = sel_idx[j];
    const float* row = g_pushed + (size_t)idx * FP1;
    const float s0 = row[0];
    const float wsum = (s0 > 0.f) ? s0 : 0.001f;
    out[(size_t)j * FDIM + t] = row[1 + t] / wsum;
}

// ---------------------------------------------------------------------------
// Launch
// Inputs (metadata order): features [N,128] f32, weights_down [N,5] f32,
//                          nidx_down [N,5] i32, sel_idx_up [N_UP,1] i32
// Output: [N_UP, 128] f32
// ---------------------------------------------------------------------------
extern "C" void kernel_launch(void* const* d_in, const int* in_sizes, int n_in,
                              void* d_out, int out_size) {
    const float* features = (const float*)d_in[0];
    const float* weights  = (const float*)d_in[1];
    const int*   nidx     = (const int*)  d_in[2];
    const int*   sel_idx  = (const int*)  d_in[3];
    float*       out      = (float*)d_out;

    const int N    = in_sizes[0] / FDIM;
    const int N_UP = in_sizes[3];

    const int f4 = NMAX / 4;  // 400000 % 4 == 0
    clear_flags_kernel<<<(f4 + 255) / 256, 256>>>(f4);
    set_flags_kernel<<<(N_UP + 255) / 256, 256>>>(sel_idx, N_UP);
    zero_sel_kernel<<<N_UP, FDIM>>>(sel_idx, N_UP);
    scatter_kernel<<<N, FDIM>>>(features, weights, nidx, N);
    gather_kernel<<<N_UP, FDIM>>>(sel_idx, out, N_UP);
}

// round 3
// speedup vs baseline: 4.0634x; 3.0069x over previous
#include <cuda_runtime.h>
#include <cstddef>

// Problem constants (fixed by the dataset)
#define NMAX   400000
#define FDIM   128
#define KNBR   5

// Split accumulator layout (16B-aligned feature rows for vec4 atomics):
//   g_wsum[i]          : accumulated weight sum (the "ones" column)
//   g_feat[i][0..127]  : accumulated weighted features (512B rows)
__device__ float         g_wsum[NMAX];
__device__ float         g_feat[(size_t)NMAX * FDIM];
__device__ unsigned char g_flag[NMAX];

// v4 float reduction to global memory (PTX ISA 8.1+, sm_90+)
__device__ __forceinline__ void red_add_v4(float* p, float4 v) {
    asm volatile("red.global.add.v4.f32 [%0], {%1,%2,%3,%4};"
                 :: "l"(p), "f"(v.x), "f"(v.y), "f"(v.z), "f"(v.w)
                 : "memory");
}

// ---------------------------------------------------------------------------
// Phase 0a: clear flags (400 KB as ints)
// ---------------------------------------------------------------------------
__global__ void clear_flags_kernel(int n4) {
    int i = blockIdx.x * blockDim.x + threadIdx.x;
    if (i < n4) reinterpret_cast<int*>(g_flag)[i] = 0;
}

// ---------------------------------------------------------------------------
// Phase 0b (fused): set flag + zero the selected row.
// One warp per selected j: lanes store float4 zeros (duplicates benign).
// ---------------------------------------------------------------------------
__global__ void prep_sel_kernel(const int* __restrict__ sel_idx, int n_up) {
    const int warp = (blockIdx.x * blockDim.x + threadIdx.x) >> 5;
    const int lane = threadIdx.x & 31;
    if (warp >= n_up) return;
    const int idx = sel_idx[warp];                 // broadcast load
    if (lane == 0) {
        g_flag[idx] = 1;
        g_wsum[idx] = 0.f;
    }
    float4* row4 = reinterpret_cast<float4*>(g_feat + (size_t)idx * FDIM);
    row4[lane] = make_float4(0.f, 0.f, 0.f, 0.f);
}

// ---------------------------------------------------------------------------
// Phase 2: scatter, one WARP per source row.
// - lanes 0..4 fetch (idx, flag, weight) in parallel, shuffle-broadcast
// - skip feature load if no live destination (~29% of rows)
// - one red.global.add.v4.f32 per lane per live edge (128 floats/edge/warp)
// ---------------------------------------------------------------------------
__global__ void scatter_kernel(const float* __restrict__ features,
                               const float* __restrict__ weights,
                               const int*   __restrict__ nidx,
                               int N) {
    const int warp = (blockIdx.x * blockDim.x + threadIdx.x) >> 5;
    const int lane = threadIdx.x & 31;
    if (warp >= N) return;
    const int i = warp;

    // Parallel prologue: lanes 0..4 each load one edge's idx / flag / weight.
    int   my_idx = -1;
    float my_w   = 0.f;
    int   my_live = 0;
    if (lane < KNBR) {
        my_idx = nidx[i * KNBR + lane];
        if (my_idx >= 0 && g_flag[my_idx] != 0) {
            my_live = 1;
            my_w = weights[i * KNBR + lane];
        }
    }
    const unsigned live_mask = __ballot_sync(0xFFFFFFFFu, my_live);
    if (live_mask == 0u) return;                   // no live dest: skip everything

    // Coalesced feature load: 32 lanes x float4 = 128 floats.
    const float4 f = reinterpret_cast<const float4*>(features)[(size_t)i * 32 + lane];

#pragma unroll
    for (int k = 0; k < KNBR; ++k) {
        if (live_mask & (1u << k)) {
            const int   idx = __shfl_sync(0xFFFFFFFFu, my_idx, k);
            const float wk  = __shfl_sync(0xFFFFFFFFu, my_w,   k);
            float* row = g_feat + (size_t)idx * FDIM + lane * 4;
            red_add_v4(row, make_float4(wk * f.x, wk * f.y, wk * f.z, wk * f.w));
            if (lane == 0) atomicAdd(g_wsum + idx, wk);
        }
    }
}

// ---------------------------------------------------------------------------
// Phase 3: gather + normalize. One warp per output row.
// wsum = relu(s0); if <=0 -> 0.001; out = feat / wsum
// ---------------------------------------------------------------------------
__global__ void gather_kernel(const int* __restrict__ sel_idx,
                              float* __restrict__ out,
                              int n_up) {
    const int warp = (blockIdx.x * blockDim.x + threadIdx.x) >> 5;
    const int lane = threadIdx.x & 31;
    if (warp >= n_up) return;
    const int idx = sel_idx[warp];
    const float s0 = g_wsum[idx];
    const float inv = 1.0f / ((s0 > 0.f) ? s0 : 0.001f);
    const float4 f = reinterpret_cast<const float4*>(g_feat + (size_t)idx * FDIM)[lane];
    reinterpret_cast<float4*>(out)[(size_t)warp * 32 + lane] =
        make_float4(f.x * inv, f.y * inv, f.z * inv, f.w * inv);
}

// ---------------------------------------------------------------------------
// Launch
// Inputs (metadata order): features [N,128] f32, weights_down [N,5] f32,
//                          nidx_down [N,5] i32, sel_idx_up [N_UP,1] i32
// Output: [N_UP, 128] f32
// ---------------------------------------------------------------------------
extern "C" void kernel_launch(void* const* d_in, const int* in_sizes, int n_in,
                              void* d_out, int out_size) {
    const float* features = (const float*)d_in[0];
    const float* weights  = (const float*)d_in[1];
    const int*   nidx     = (const int*)  d_in[2];
    const int*   sel_idx  = (const int*)  d_in[3];
    float*       out      = (float*)d_out;

    const int N    = in_sizes[0] / FDIM;
    const int N_UP = in_sizes[3];

    const int f4 = NMAX / 4;  // 400000 % 4 == 0
    clear_flags_kernel<<<(f4 + 255) / 256, 256>>>(f4);

    // 8 warps per 256-thread block
    const int WPB = 8;
    prep_sel_kernel<<<(N_UP + WPB - 1) / WPB, WPB * 32>>>(sel_idx, N_UP);
    scatter_kernel<<<(N + WPB - 1) / WPB, WPB * 32>>>(features, weights, nidx, N);
    gather_kernel<<<(N_UP + WPB - 1) / WPB, WPB * 32>>>(sel_idx, out, N_UP);
}